// round 2
// baseline (speedup 1.0000x reference)
#include <cuda_runtime.h>
#include <cstdint>

// ---------------------------------------------------------------------------
// Runflow, T = 1<<20.
//  K1 prep : coalesced read of x(T,9); compute D = a*prec-evc, cg, ci;
//            write them TRANSPOSED (iteration-major for the scan kernel)
//            via smem transpose. Also zeroes lookback flags.
//  K2 ppq  : pp contraction scan (64-step warmup, Lipschitz 0.71/step),
//            fused with q = q_green + q_imperv; writes q via smem transpose
//            (coalesced). 32768 threads x 32 outputs.
//  K3 scan : shift + linear recurrence h' = wr1*h + wr2*q_shift via
//            single-pass decoupled lookback; writes final output.
// ---------------------------------------------------------------------------

#define T_TOTAL   (1 << 20)

// K2 geometry
#define NT_B      32768           // scan threads
#define PP_C      32              // outputs per thread (NT_B*PP_C == T)
#define B_BLK     128             // blocks (B_BLK*256 == NT_B)

// K1 geometry
#define P_ROWS    1024            // rows per prep block
#define P_BLKS    (T_TOTAL / P_ROWS)

// K3 geometry
#define S_NB      1024            // scan blocks
#define S_BT      256             // threads
#define S_CH      4               // elems/thread (S_NB*S_BT*S_CH == T)

// Scratch (device globals — no allocation allowed)
__device__ float  g_Dt[T_TOTAL];     // transposed: [e*NT_B + tid]
__device__ float2 g_cct[T_TOTAL];    // transposed (cg, ci)
__device__ float  g_q[T_TOTAL];      // q, natural layout
// decoupled-lookback state
__device__ float  g_pA[S_NB], g_pB[S_NB];   // inclusive prefix pairs
__device__ float  g_aA[S_NB], g_aB[S_NB];   // block aggregate pairs
__device__ int    g_flag[S_NB];             // 0=none 1=agg 2=prefix

// ---------------------------------------------------------------------------
// K1: prep. Block handles 1024 rows. Stage x through smem (float4 coalesced),
// compute per-row constants, transpose-write into iteration-major layout.
// ---------------------------------------------------------------------------
__global__ void __launch_bounds__(1024) k_prep(
    const float* __restrict__ x,
    const float* __restrict__ f0p, const float* __restrict__ fcp,
    const float* __restrict__ kp,  const float* __restrict__ np,
    const float* __restrict__ evp, const float* __restrict__ evcp)
{
    __shared__ float tile[P_ROWS * 9];   // 36 KB
    const int b = blockIdx.x;
    const int t = threadIdx.x;

    if (b == 0) g_flag[t] = 0;           // reset lookback flags (t < 1024 == S_NB)

    // stage x rows [b*1024, +1024): 2304 float4s
    const float4* src = reinterpret_cast<const float4*>(x) + (size_t)b * (P_ROWS * 9 / 4);
    float4* t4 = reinterpret_cast<float4*>(tile);
    for (int i = t; i < P_ROWS * 9 / 4; i += 1024) t4[i] = src[i];
    __syncthreads();

    const float f0 = f0p[0], fc = fcp[0], kk = kp[0], nn = np[0];
    const float a  = 1.0f - evp[0], evc = evcp[0];

    // one row per thread (stride 9 is coprime with 32 banks -> conflict-free)
    const int base = 9 * t;
    const float gl = tile[base + 0];
    const float im = tile[base + 2];
    const float ar = tile[base + 3];
    const float sl = tile[base + 4];
    const float pr = tile[base + 6];
    const float tp = tile[base + 7];

    const float ft = (f0 - fc) * __expf(-(kk * tp)) + fc;
    const float cg = gl * ar * (1.0f - ft) * 1e-3f;
    const float ci = (1.49f / nn) * sqrtf(im * ar) * sqrtf(sl);
    const float D  = a * pr - evc;
    __syncthreads();

    // re-stage into padded layout f(r) = r + (r>>5) for conflict-free transpose
    const int fr = t + (t >> 5);
    tile[fr]          = D;
    tile[1056 + fr]   = cg;
    tile[2112 + fr]   = ci;
    __syncthreads();

    // transposed write: warp w == iteration e', lane l == local thread index
    // row r = 32*l + w; scan-thread index = b*32 + l
    const int w = t >> 5, l = t & 31;
    const int fi = 33 * l + w;                 // f(32*l + w)
    const int dst = w * NT_B + b * 32 + l;     // coalesced 128B per warp
    g_Dt[dst]  = tile[fi];
    g_cct[dst] = make_float2(tile[1056 + fi], tile[2112 + fi]);
}

// one pp step: min/max of two affine maps (dependent chain: FFMA + FMNMX)
__device__ __forceinline__ float ppstep(float c, float D,
                                        float A1, float A2, float Kc, bool mn)
{
    const float t1 = fmaf(c, A1, D);
    const float t2 = fmaf(c, A2, D + Kc);
    return mn ? fminf(t1, t2) : fmaxf(t1, t2);
}

// ---------------------------------------------------------------------------
// K2: pp scan fused with q. Thread tid owns rows [tid*32, tid*32+32).
// Warmup over the 64 preceding rows (exact from pp0 when window reaches 0).
// All global accesses coalesced (iteration-major layout / smem transpose).
// ---------------------------------------------------------------------------
__global__ void __launch_bounds__(256) k_ppq(
    const float* __restrict__ x,
    const float* __restrict__ evp,  const float* __restrict__ mrp,
    const float* __restrict__ missp,const float* __restrict__ dpp)
{
    __shared__ float sq[256 * 33];   // padded transpose buffer (33 KB)
    const int lt  = threadIdx.x;
    const int tid = blockIdx.x * 256 + lt;

    const float a    = 1.0f - evp[0];
    const float miss = missp[0];
    const float mr   = mrp[0];
    const float dp   = dpp[0];
    const float A1   = a;
    const float A2   = a * miss;
    const float Kc   = a * mr * (1.0f - miss);
    const bool  mn   = (A2 <= A1);

    const float pp0 = x[7] - x[6];
    float c = (tid <= 2) ? pp0 : 0.0f;

    // warmup over predecessor threads' rows (coalesced: lanes read consecutive)
    const int t0 = (tid >= 2) ? (tid - 2) : 0;
    for (int tp = t0; tp < tid; ++tp) {
#pragma unroll
        for (int e = 0; e < 32; ++e)
            c = ppstep(c, g_Dt[e * NT_B + tp], A1, A2, Kc, mn);
    }

    // main: emit q for each owned row
    const float e53 = 5.0f / 3.0f;
#pragma unroll 8
    for (int e = 0; e < 32; ++e) {
        const int idx = e * NT_B + tid;
        const float  D  = g_Dt[idx];
        const float2 cc = g_cct[idx];
        const float pre = fmaxf(c, 0.0f);
        const float qg  = fmaxf(pre * cc.x, 0.0f);
        const float d   = fmaxf(pre * 1e-3f - dp, 0.0f);
        const float qi  = fmaxf(cc.y * __powf(d, e53), 0.0f);
        sq[lt * 33 + e] = qg + qi;
        c = ppstep(c, D, A1, A2, Kc, mn);
    }
    __syncthreads();

    // coalesced write-out of the block's 8192 q values
    const int b8 = blockIdx.x * 8192;
#pragma unroll
    for (int k = 0; k < 32; ++k) {
        const int i = k * 256 + lt;
        g_q[b8 + i] = sq[(i >> 5) * 33 + (i & 31)];
    }
}

// ---------------------------------------------------------------------------
// K3: shifted linear recurrence, single-pass decoupled lookback.
// pair (A,B): h_out = A*h_in + B ; combine(f,g) = (fA*gA, fB*gA + gB)
// ---------------------------------------------------------------------------
__global__ void __launch_bounds__(256) k_scan(
    const float* __restrict__ x,
    const float* __restrict__ wr1p, const float* __restrict__ wr2p,
    const float* __restrict__ wz1p, const float* __restrict__ wz2p,
    const void*  __restrict__ epochp,
    float* __restrict__ out)
{
    const int blk  = blockIdx.x;
    const int t    = threadIdx.x;
    const int lane = t & 31;
    const int wid  = t >> 5;

    const float wr1 = wr1p[0], wr2 = wr2p[0];
    const float wz1 = wz1p[0], wz2 = wz2p[0];

    int epoch;
    {
        const int iv = *reinterpret_cast<const int*>(epochp);
        if (iv >= 0 && iv < 1000000) epoch = iv;
        else epoch = (int)(*reinterpret_cast<const float*>(epochp));
    }
    const bool pass2 = (epoch > 10);

    const float rid  = rintf(x[8]);
    const int  shift = (rid == 3723.0f || rid == 870.0f) ? 1 : 4;

    const int base = blk * (S_BT * S_CH) + t * S_CH;

    // load q_shift (coalesced scalar loads; handles shift-misalignment)
    float qv[S_CH];
#pragma unroll
    for (int e = 0; e < S_CH; ++e) {
        const int j = base + e - shift;
        qv[e] = (j >= 0) ? g_q[j] : 0.0f;
    }

    // thread-local pair
    float A = 1.0f, B = 0.0f;
#pragma unroll
    for (int e = 0; e < S_CH; ++e) {
        const float sv = (base + e == 0) ? 0.0f : wr2 * qv[e];
        B = fmaf(B, wr1, sv);
        A *= wr1;
    }

    // warp inclusive scan of pairs
#pragma unroll
    for (int d = 1; d < 32; d <<= 1) {
        const float pa = __shfl_up_sync(0xFFFFFFFFu, A, d);
        const float pb = __shfl_up_sync(0xFFFFFFFFu, B, d);
        if (lane >= d) { B = fmaf(pb, A, B); A *= pa; }
    }
    // thread exclusive within warp
    float eA = __shfl_up_sync(0xFFFFFFFFu, A, 1);
    float eB = __shfl_up_sync(0xFFFFFFFFu, B, 1);
    if (lane == 0) { eA = 1.0f; eB = 0.0f; }

    __shared__ float sWA[8], sWB[8];
    __shared__ float sExB;
    if (lane == 31) { sWA[wid] = A; sWB[wid] = B; }
    __syncthreads();

    if (t == 0) {
        // warp aggregates -> warp exclusive prefixes; (aa,bb) = block aggregate
        float aa = 1.0f, bb = 0.0f;
#pragma unroll
        for (int w = 0; w < 8; ++w) {
            const float ta = sWA[w], tb = sWB[w];
            sWA[w] = aa; sWB[w] = bb;
            bb = fmaf(bb, ta, tb);
            aa *= ta;
        }

        float exA = 1.0f, exB = 0.0f;
        volatile int*   vf  = g_flag;
        volatile float* vpA = g_pA;  volatile float* vpB = g_pB;
        volatile float* vaA = g_aA;  volatile float* vaB = g_aB;

        if (blk == 0) {
            vpA[0] = aa; vpB[0] = bb;
            __threadfence();
            vf[0] = 2;
        } else {
            vaA[blk] = aa; vaB[blk] = bb;
            __threadfence();
            vf[blk] = 1;

            float accA = 1.0f, accB = 0.0f;   // composition of (p, blk-1]
            int p = blk - 1;
            while (true) {
                int f;
                do { f = vf[p]; } while (f == 0);
                __threadfence();
                if (f == 2) {
                    const float pa = vpA[p], pb = vpB[p];
                    exA = pa * accA;
                    exB = fmaf(pb, accA, accB);
                    break;
                } else {
                    const float qa = vaA[p], qb = vaB[p];
                    accB = fmaf(qb, accA, accB);
                    accA = qa * accA;
                    --p;
                }
            }
            vpA[blk] = exA * aa;
            vpB[blk] = fmaf(exB, aa, bb);
            __threadfence();
            vf[blk] = 2;
        }
        sExB = exB;
    }
    __syncthreads();

    // combined exclusive prefix: blockExcl -> warpExcl -> threadExcl (h0 = 0)
    const float wAx = sWA[wid], wBx = sWB[wid];
    const float bB  = fmaf(sExB, wAx, wBx);
    float h = fmaf(bB, eA, eB);

    float ov[S_CH];
#pragma unroll
    for (int e = 0; e < S_CH; ++e) {
        const int gi = base + e;
        const float q  = qv[e];
        const float sv = (gi == 0) ? 0.0f : wr2 * q;
        h = fmaf(h, wr1, sv);
        float o = fmaf(h, wz1, wz2 * q);
        if (gi == 0) o = q;
        ov[e] = pass2 ? o : q;
    }
    *reinterpret_cast<float4*>(out + base) = make_float4(ov[0], ov[1], ov[2], ov[3]);
}

// ---------------------------------------------------------------------------
// kernel_launch
// Inputs: 0:x 1:f_0 2:f_c 3:k 4:n 5:d_p 6:evap 7:evap_constant
//         8:missing_restrict 9:missing 10:w_r_1 11:w_r_2 12:w_z_1 13:w_z_2
//         14:epoch
// ---------------------------------------------------------------------------
extern "C" void kernel_launch(void* const* d_in, const int* in_sizes, int n_in,
                              void* d_out, int out_size)
{
    (void)in_sizes; (void)n_in; (void)out_size;
    const float* x    = (const float*)d_in[0];
    const float* f0p  = (const float*)d_in[1];
    const float* fcp  = (const float*)d_in[2];
    const float* kp   = (const float*)d_in[3];
    const float* np   = (const float*)d_in[4];
    const float* dpp  = (const float*)d_in[5];
    const float* evp  = (const float*)d_in[6];
    const float* evcp = (const float*)d_in[7];
    const float* mrp  = (const float*)d_in[8];
    const float* missp= (const float*)d_in[9];
    const float* wr1p = (const float*)d_in[10];
    const float* wr2p = (const float*)d_in[11];
    const float* wz1p = (const float*)d_in[12];
    const float* wz2p = (const float*)d_in[13];
    const void*  epochp = d_in[14];
    float* out = (float*)d_out;

    k_prep<<<P_BLKS, 1024>>>(x, f0p, fcp, kp, np, evp, evcp);
    k_ppq <<<B_BLK, 256>>>(x, evp, mrp, missp, dpp);
    k_scan<<<S_NB, S_BT>>>(x, wr1p, wr2p, wz1p, wz2p, epochp, out);
}

// round 3
// speedup vs baseline: 2.6606x; 2.6606x over previous
#include <cuda_runtime.h>
#include <cstdint>

// ---------------------------------------------------------------------------
// Runflow, T = 1<<20.
//  K1 prep : read x(T,9) coalesced via smem; D = a*prec-evc, cg, ci written
//            TRANSPOSED (iteration-major). Zeroes lookback flags.
//  K2 ppq  : pp contraction scan (64-step warmup, L = 0.71/step) fused with
//            q computation; coalesced in (transposed) and out (smem transpose).
//  K3 scan : shift + linear recurrence via single-pass decoupled lookback
//            with WARP-PARALLEL window (32 predecessors/step).
// ---------------------------------------------------------------------------

#define T_TOTAL   (1 << 20)

// K2 geometry
#define NT_B      32768           // scan threads total
#define B_BLK     256             // blocks
#define B_THR     128             // threads/block  (B_BLK*B_THR == NT_B)

// K1 geometry
#define P_ROWS    1024            // rows per prep block
#define P_THR     512
#define P_BLKS    (T_TOTAL / P_ROWS)

// K3 geometry
#define S_NB      256             // scan blocks
#define S_BT      256             // threads
#define S_CH      16              // elems/thread (S_NB*S_BT*S_CH == T)
#define S_ELEMS   (S_BT * S_CH)   // 4096 per block

// Scratch (device globals — no allocation allowed)
__device__ float  g_Dt[T_TOTAL];     // transposed: [e*NT_B + tid]
__device__ float2 g_cct[T_TOTAL];    // transposed (cg, ci)
__device__ float  g_q[T_TOTAL];      // q, natural layout
// decoupled-lookback state
__device__ float  g_pA[S_NB], g_pB[S_NB];   // inclusive prefix pairs
__device__ float  g_aA[S_NB], g_aB[S_NB];   // block aggregate pairs
__device__ int    g_flag[S_NB];             // 0=none 1=agg 2=prefix

// ---------------------------------------------------------------------------
// K1: prep. Block of 512 threads handles 1024 rows (2 rows/thread).
// ---------------------------------------------------------------------------
__global__ void __launch_bounds__(P_THR) k_prep(
    const float* __restrict__ x,
    const float* __restrict__ f0p, const float* __restrict__ fcp,
    const float* __restrict__ kp,  const float* __restrict__ np,
    const float* __restrict__ evp, const float* __restrict__ evcp)
{
    __shared__ float tile[P_ROWS * 9];   // 36 KB
    const int b = blockIdx.x;
    const int t = threadIdx.x;

    if (b == 0 && t < S_NB) g_flag[t] = 0;   // reset lookback flags

    // stage 1024 rows = 2304 float4 (4-5 per thread -> good MLP)
    const float4* src = reinterpret_cast<const float4*>(x) + (size_t)b * (P_ROWS * 9 / 4);
    float4* t4 = reinterpret_cast<float4*>(tile);
#pragma unroll
    for (int k = 0; k < 5; ++k) {
        const int i = t + k * P_THR;
        if (i < P_ROWS * 9 / 4) t4[i] = src[i];
    }
    __syncthreads();

    const float f0 = f0p[0], fc = fcp[0], kk = kp[0], nn = np[0];
    const float a  = 1.0f - evp[0], evc = evcp[0];

    float Dv[2], cgv[2], civ[2];
#pragma unroll
    for (int k = 0; k < 2; ++k) {
        const int r    = t + k * P_THR;
        const int base = 9 * r;                 // stride 9: conflict-free
        const float gl = tile[base + 0];
        const float im = tile[base + 2];
        const float ar = tile[base + 3];
        const float sl = tile[base + 4];
        const float pr = tile[base + 6];
        const float tp = tile[base + 7];
        const float ft = (f0 - fc) * __expf(-(kk * tp)) + fc;
        cgv[k] = gl * ar * (1.0f - ft) * 1e-3f;
        civ[k] = (1.49f / nn) * sqrtf(im * ar) * sqrtf(sl);
        Dv[k]  = a * pr - evc;
    }
    __syncthreads();

    // padded restage f(r) = r + (r>>5): D | cg | ci at offsets 0/1056/2112
#pragma unroll
    for (int k = 0; k < 2; ++k) {
        const int r  = t + k * P_THR;
        const int fr = r + (r >> 5);
        tile[fr]        = Dv[k];
        tile[1056 + fr] = cgv[k];
        tile[2112 + fr] = civ[k];
    }
    __syncthreads();

    // transposed write: idx -> (w = e, l = lane); row = 32*l + w
#pragma unroll
    for (int k = 0; k < 2; ++k) {
        const int idx = t + k * P_THR;
        const int w = idx >> 5, l = idx & 31;
        const int fi  = 33 * l + w;             // f(32*l + w), stride-33 read
        const int dst = w * NT_B + b * 32 + l;  // coalesced per warp
        g_Dt[dst]  = tile[fi];
        g_cct[dst] = make_float2(tile[1056 + fi], tile[2112 + fi]);
    }
}

// one pp step: min/max of two affine maps (chain: FFMA + FMNMX)
__device__ __forceinline__ float ppstep(float c, float D,
                                        float A1, float A2, float Kc, bool mn)
{
    const float t1 = fmaf(c, A1, D);
    const float t2 = fmaf(c, A2, D + Kc);
    return mn ? fminf(t1, t2) : fmaxf(t1, t2);
}

// ---------------------------------------------------------------------------
// K2: pp scan fused with q. Thread tid owns rows [tid*32, tid*32+32).
// ---------------------------------------------------------------------------
__global__ void __launch_bounds__(B_THR) k_ppq(
    const float* __restrict__ x,
    const float* __restrict__ evp,  const float* __restrict__ mrp,
    const float* __restrict__ missp,const float* __restrict__ dpp)
{
    __shared__ float sq[B_THR * 33];   // padded transpose buffer (16.9 KB)
    const int lt  = threadIdx.x;
    const int tid = blockIdx.x * B_THR + lt;

    const float a    = 1.0f - evp[0];
    const float miss = missp[0];
    const float mr   = mrp[0];
    const float dp   = dpp[0];
    const float A1   = a;
    const float A2   = a * miss;
    const float Kc   = a * mr * (1.0f - miss);
    const bool  mn   = (A2 <= A1);

    const float pp0 = x[7] - x[6];
    float c = (tid <= 2) ? pp0 : 0.0f;

    // warmup over the two predecessor threads' rows (64 steps, coalesced)
    const int t0 = (tid >= 2) ? (tid - 2) : 0;
    for (int tp = t0; tp < tid; ++tp) {
#pragma unroll
        for (int e = 0; e < 32; ++e)
            c = ppstep(c, g_Dt[e * NT_B + tp], A1, A2, Kc, mn);
    }

    // main: emit q for each owned row
    const float e53 = 5.0f / 3.0f;
#pragma unroll 8
    for (int e = 0; e < 32; ++e) {
        const int idx = e * NT_B + tid;
        const float  D  = g_Dt[idx];
        const float2 cc = g_cct[idx];
        const float pre = fmaxf(c, 0.0f);
        const float qg  = fmaxf(pre * cc.x, 0.0f);
        const float d   = fmaxf(pre * 1e-3f - dp, 0.0f);
        const float qi  = fmaxf(cc.y * __powf(d, e53), 0.0f);
        sq[lt * 33 + e] = qg + qi;
        c = ppstep(c, D, A1, A2, Kc, mn);
    }
    __syncthreads();

    // coalesced write-out of the block's 4096 q values
    const int b4 = blockIdx.x * (B_THR * 32);
#pragma unroll
    for (int k = 0; k < 32; ++k) {
        const int i = k * B_THR + lt;
        g_q[b4 + i] = sq[(i >> 5) * 33 + (i & 31)];
    }
}

// ---------------------------------------------------------------------------
// K3: shifted linear recurrence, decoupled lookback with warp-parallel window.
// pair (A,B): h_out = A*h_in + B ; combine(first f, then g) = (fA*gA, fB*gA+gB)
// ---------------------------------------------------------------------------
__device__ __forceinline__ int spad(int i) { return i + (i >> 5); }

__global__ void __launch_bounds__(S_BT) k_scan(
    const float* __restrict__ x,
    const float* __restrict__ wr1p, const float* __restrict__ wr2p,
    const float* __restrict__ wz1p, const float* __restrict__ wz2p,
    const void*  __restrict__ epochp,
    float* __restrict__ out)
{
    __shared__ float sq[S_ELEMS + (S_ELEMS >> 5)];   // padded (16.5 KB)
    __shared__ float sWA[8], sWB[8];
    __shared__ float sAggA, sAggB, sE;

    const int blk  = blockIdx.x;
    const int t    = threadIdx.x;
    const int lane = t & 31;
    const int wid  = t >> 5;

    const float wr1 = wr1p[0], wr2 = wr2p[0];
    const float wz1 = wz1p[0], wz2 = wz2p[0];

    int epoch;
    {
        const int iv = *reinterpret_cast<const int*>(epochp);
        if (iv >= 0 && iv < 1000000) epoch = iv;
        else epoch = (int)(*reinterpret_cast<const float*>(epochp));
    }
    const bool pass2 = (epoch > 10);

    const float rid  = rintf(x[8]);
    const int  shift = (rid == 3723.0f || rid == 870.0f) ? 1 : 4;

    const int gbase = blk * S_ELEMS;

    // stage q_shift for this block (coalesced global reads)
#pragma unroll
    for (int k = 0; k < S_CH; ++k) {
        const int i  = k * S_BT + t;
        const int j  = gbase + i - shift;
        sq[spad(i)] = (j >= 0) ? g_q[j] : 0.0f;
    }
    __syncthreads();

    // thread-local chunk + pair
    float qv[S_CH];
    float A = 1.0f, B = 0.0f;
    const int tb = t * S_CH;
#pragma unroll
    for (int e = 0; e < S_CH; ++e) {
        const float q = sq[spad(tb + e)];
        qv[e] = q;
        const float sv = (gbase + tb + e == 0) ? 0.0f : wr2 * q;
        B = fmaf(B, wr1, sv);
        A *= wr1;
    }

    // warp inclusive scan of pairs
#pragma unroll
    for (int d = 1; d < 32; d <<= 1) {
        const float pa = __shfl_up_sync(0xFFFFFFFFu, A, d);
        const float pb = __shfl_up_sync(0xFFFFFFFFu, B, d);
        if (lane >= d) { B = fmaf(pb, A, B); A *= pa; }
    }
    float eA = __shfl_up_sync(0xFFFFFFFFu, A, 1);
    float eB = __shfl_up_sync(0xFFFFFFFFu, B, 1);
    if (lane == 0) { eA = 1.0f; eB = 0.0f; }
    if (lane == 31) { sWA[wid] = A; sWB[wid] = B; }
    __syncthreads();

    if (t == 0) {  // warp aggregates -> warp exclusive prefixes + block agg
        float aa = 1.0f, bb = 0.0f;
#pragma unroll
        for (int w = 0; w < 8; ++w) {
            const float ta = sWA[w], tb2 = sWB[w];
            sWA[w] = aa; sWB[w] = bb;
            bb = fmaf(bb, ta, tb2);
            aa *= ta;
        }
        sAggA = aa; sAggB = bb;
    }
    __syncthreads();

    // ---- warp 0: decoupled lookback (32-wide window) ----
    if (wid == 0) {
        const float aa = sAggA, bb = sAggB;
        volatile int*   vf  = g_flag;
        volatile float* vpA = g_pA;  volatile float* vpB = g_pB;
        volatile float* vaA = g_aA;  volatile float* vaB = g_aB;

        if (blk == 0) {
            if (lane == 0) {
                vpA[0] = aa; vpB[0] = bb;
                __threadfence();
                vf[0] = 2;
                sE = 0.0f;
            }
        } else {
            if (lane == 0) {
                vaA[blk] = aa; vaB[blk] = bb;
                __threadfence();
                vf[blk] = 1;
            }
            float accA = 1.0f, accB = 0.0f;   // composition of (window end, blk)
            float EA = 1.0f, EB = 0.0f;
            int wend = blk;
            while (true) {
                const int p = wend - 1 - lane;  // lane 0 = closest predecessor
                int f = 0;
                float xA = 1.0f, xB = 0.0f;
                if (p >= 0) {
                    do { f = vf[p]; } while (f == 0);
                    __threadfence();
                    if (f == 2) { xA = vpA[p]; xB = vpB[p]; }
                    else        { xA = vaA[p]; xB = vaB[p]; }
                }
                const unsigned m2 = __ballot_sync(0xFFFFFFFFu, (p >= 0) && (f == 2));
                float yA = xA, yB = xB;
                int l2 = 32;
                if (m2) {
                    l2 = __ffs(m2) - 1;         // closest prefix in window
                    if (lane > l2) { yA = 1.0f; yB = 0.0f; }  // beyond prefix
                }
                // ordered reduce: earlier blocks live at HIGHER lanes
#pragma unroll
                for (int d = 1; d < 32; d <<= 1) {
                    const float oA = __shfl_down_sync(0xFFFFFFFFu, yA, d);
                    const float oB = __shfl_down_sync(0xFFFFFFFFu, yB, d);
                    if (lane + d < 32) { yB = fmaf(oB, yA, yB); yA *= oA; }
                }
                const float wA = __shfl_sync(0xFFFFFFFFu, yA, 0);
                const float wB = __shfl_sync(0xFFFFFFFFu, yB, 0);
                // acc <- combine(window, acc)
                const float nB = fmaf(wB, accA, accB);
                const float nA = wA * accA;
                if (m2) { EA = nA; EB = nB; break; }
                accA = nA; accB = nB;
                wend -= 32;
                if (wend <= 0) { EA = nA; EB = nB; break; }  // hit the start
            }
            if (lane == 0) {
                vpA[blk] = EA * aa;
                vpB[blk] = fmaf(EB, aa, bb);
                __threadfence();
                vf[blk] = 2;
                sE = EB;   // block-incoming h (h0 = 0)
            }
        }
    }
    __syncthreads();

    // combined: block h_in -> warp h_in -> thread h_in
    const float hb = sE;
    const float hw = fmaf(hb, sWA[wid], sWB[wid]);
    float h = fmaf(hw, eA, eB);

#pragma unroll
    for (int e = 0; e < S_CH; ++e) {
        const int gi = gbase + tb + e;
        const float q  = qv[e];
        const float sv = (gi == 0) ? 0.0f : wr2 * q;
        h = fmaf(h, wr1, sv);
        float o = fmaf(h, wz1, wz2 * q);
        if (gi == 0) o = q;
        sq[spad(tb + e)] = pass2 ? o : q;
    }
    __syncthreads();

    // coalesced store
#pragma unroll
    for (int k = 0; k < S_CH; ++k) {
        const int i = k * S_BT + t;
        out[gbase + i] = sq[spad(i)];
    }
}

// ---------------------------------------------------------------------------
// kernel_launch
// ---------------------------------------------------------------------------
extern "C" void kernel_launch(void* const* d_in, const int* in_sizes, int n_in,
                              void* d_out, int out_size)
{
    (void)in_sizes; (void)n_in; (void)out_size;
    const float* x    = (const float*)d_in[0];
    const float* f0p  = (const float*)d_in[1];
    const float* fcp  = (const float*)d_in[2];
    const float* kp   = (const float*)d_in[3];
    const float* np   = (const float*)d_in[4];
    const float* dpp  = (const float*)d_in[5];
    const float* evp  = (const float*)d_in[6];
    const float* evcp = (const float*)d_in[7];
    const float* mrp  = (const float*)d_in[8];
    const float* missp= (const float*)d_in[9];
    const float* wr1p = (const float*)d_in[10];
    const float* wr2p = (const float*)d_in[11];
    const float* wz1p = (const float*)d_in[12];
    const float* wz2p = (const float*)d_in[13];
    const void*  epochp = d_in[14];
    float* out = (float*)d_out;

    k_prep<<<P_BLKS, P_THR>>>(x, f0p, fcp, kp, np, evp, evcp);
    k_ppq <<<B_BLK, B_THR>>>(x, evp, mrp, missp, dpp);
    k_scan<<<S_NB, S_BT>>>(x, wr1p, wr2p, wz1p, wz2p, epochp, out);
}

// round 5
// speedup vs baseline: 2.9004x; 1.0901x over previous
#include <cuda_runtime.h>
#include <cstdint>

// ---------------------------------------------------------------------------
// Runflow, T = 1<<20, TWO kernels:
//  K1 fused : per block of 2048 rows — stage x coalesced -> smem, extract
//             D/cg/ci into skewed smem columns, pp contraction scan
//             (48-step warmup, Lipschitz 0.71/step; exact from pp0 at start),
//             q computed inline, written coalesced to g_q. Zeroes flags.
//  K2 scan  : shift + linear recurrence via decoupled lookback
//             (warp-parallel window), writes final output.
// ---------------------------------------------------------------------------

#define T_TOTAL   (1 << 20)

// K1 geometry
#define R_BLK     2048            // rows per block
#define F_THR     512             // threads
#define F_BLKS    (T_TOTAL / R_BLK)   // 512 blocks
#define C_ROWS    512             // rows per chunk
#define N_CH      (R_BLK / C_ROWS)    // 4 chunks
#define W_UP      48              // warmup steps (0.71^48 ~ 7e-8)
#define OWN       (R_BLK / F_THR)     // 4 rows per thread

// skew for conflict-free strided smem access (macro: usable in array extents)
#define SKW(i)    ((i) + ((i) >> 3))

// K2 geometry
#define S_NB      256
#define S_BT      256
#define S_CH      16              // S_NB*S_BT*S_CH == T
#define S_ELEMS   (S_BT * S_CH)

// Scratch (device globals — no allocation allowed)
__device__ float g_q[T_TOTAL];
__device__ float g_pA[S_NB], g_pB[S_NB];
__device__ float g_aA[S_NB], g_aB[S_NB];
__device__ int   g_flag[S_NB];

__device__ __forceinline__ int skw(int i) { return SKW(i); }

// pp step: c' = min/max of two affine maps (chain: FFMA + FMNMX)
__device__ __forceinline__ float ppstep(float c, float D,
                                        float A1, float A2, float Kc, bool mn)
{
    const float t1 = fmaf(c, A1, D);
    const float t2 = fmaf(c, A2, D + Kc);
    return mn ? fminf(t1, t2) : fmaxf(t1, t2);
}

// ---------------------------------------------------------------------------
// K1: fused prep + pp scan + q
// ---------------------------------------------------------------------------
__global__ void __launch_bounds__(F_THR) k_fused(
    const float* __restrict__ x,
    const float* __restrict__ f0p, const float* __restrict__ fcp,
    const float* __restrict__ kp,  const float* __restrict__ np,
    const float* __restrict__ evp, const float* __restrict__ evcp,
    const float* __restrict__ mrp, const float* __restrict__ missp,
    const float* __restrict__ dpp)
{
    __shared__ __align__(16) float stage[C_ROWS * 9];          // 4608 fl, 18 KB
    __shared__ float colD [SKW(64 + R_BLK - 1) + 2];           // ~2378 fl
    __shared__ float colCG[SKW(R_BLK - 1) + 2];                // ~2305 fl
    __shared__ float colCI[SKW(R_BLK - 1) + 2];                // ~2305 fl
    __shared__ __align__(16) float preBuf[576];                // 64 rows x 9

    const int b = blockIdx.x;
    const int t = threadIdx.x;

    if (b == 0 && t < S_NB) g_flag[t] = 0;    // reset lookback flags

    const float f0 = f0p[0], fc = fcp[0], kk = kp[0], nn = np[0];
    const float a  = 1.0f - evp[0], evc = evcp[0];
    const float miss = missp[0], mr = mrp[0], dp = dpp[0];
    const float A1 = a, A2 = a * miss;
    const float Kc = a * mr * (1.0f - miss);
    const bool  mn = (A2 <= A1);
    const float pp0 = x[7] - x[6];

    const int rowBase = b * R_BLK;
    const float4* xs = reinterpret_cast<const float4*>(x) + (size_t)rowBase * 9 / 4;

    // prologue: 64 rows before block start (144 float4), only for b>0
    if (b > 0 && t < 144)
        reinterpret_cast<float4*>(preBuf)[t] =
            reinterpret_cast<const float4*>(x)[(size_t)rowBase * 9 / 4 - 144 + t];

    // chunk 0 -> registers -> smem
    {
        float4 r0 = xs[t];
        float4 r1 = xs[t + 512];
        float4 r2 = (t < 128) ? xs[t + 1024] : make_float4(0.f, 0.f, 0.f, 0.f);
        float4* s4 = reinterpret_cast<float4*>(stage);
        s4[t] = r0; s4[t + 512] = r1;
        if (t < 128) s4[t + 1024] = r2;
    }
    __syncthreads();

    // prologue D
    if (b > 0 && t < 64)
        colD[skw(t)] = fmaf(a, preBuf[9 * t + 6], -evc);

    const float e53 = 5.0f / 3.0f;

    // extraction loop, register double-buffered
    for (int c = 0; c < N_CH; ++c) {
        float4 p0, p1, p2;
        if (c + 1 < N_CH) {
            const float4* xc = xs + (c + 1) * (C_ROWS * 9 / 4);
            p0 = xc[t]; p1 = xc[t + 512];
            if (t < 128) p2 = xc[t + 1024];
        }

        // process chunk c: row r = c*512 + t, one row per thread
        {
            const int b9 = 9 * t;                       // stride 9: conflict-free
            const float gl = stage[b9 + 0];
            const float im = stage[b9 + 2];
            const float ar = stage[b9 + 3];
            const float sl = stage[b9 + 4];
            const float pr = stage[b9 + 6];
            const float tp = stage[b9 + 7];
            const float ft = (f0 - fc) * __expf(-(kk * tp)) + fc;
            const int   r  = c * C_ROWS + t;
            colCG[skw(r)]      = gl * ar * (1.0f - ft) * 1e-3f;
            colCI[skw(r)]      = (1.49f / nn) * sqrtf(im * ar) * sqrtf(sl);
            colD [skw(64 + r)] = fmaf(a, pr, -evc);
        }
        __syncthreads();
        if (c + 1 < N_CH) {
            float4* s4 = reinterpret_cast<float4*>(stage);
            s4[t] = p0; s4[t + 512] = p1;
            if (t < 128) s4[t + 1024] = p2;
            __syncthreads();
        }
    }

    // ---- pp scan + q: thread t owns local rows [4t, 4t+4) ----
    const int sLoc = OWN * t;
    float cc;
    int   jmin;
    if (b == 0 && sLoc <= W_UP) { jmin = 0; cc = pp0; }   // exact from row 0
    else                        { jmin = sLoc - W_UP; cc = 0.0f; }

#pragma unroll
    for (int k = 0; k < W_UP; ++k) {
        const int j = sLoc - W_UP + k;
        if (j >= jmin) cc = ppstep(cc, colD[skw(64 + j)], A1, A2, Kc, mn);
    }

    float qbuf[OWN];
#pragma unroll
    for (int e = 0; e < OWN; ++e) {
        const int r   = sLoc + e;
        const float pre = fmaxf(cc, 0.0f);
        const float qg  = fmaxf(pre * colCG[skw(r)], 0.0f);
        const float d   = fmaxf(pre * 1e-3f - dp, 0.0f);
        const float qi  = fmaxf(colCI[skw(r)] * __powf(d, e53), 0.0f);
        qbuf[e] = qg + qi;
        cc = ppstep(cc, colD[skw(64 + r)], A1, A2, Kc, mn);
    }
    __syncthreads();          // stage no longer needed: reuse for q transpose

#pragma unroll
    for (int e = 0; e < OWN; ++e) stage[skw(sLoc + e)] = qbuf[e];
    __syncthreads();

    // coalesced write-out
#pragma unroll
    for (int k = 0; k < OWN; ++k) {
        const int i = k * F_THR + t;
        g_q[rowBase + i] = stage[skw(i)];
    }
}

// ---------------------------------------------------------------------------
// K2: shifted linear recurrence, decoupled lookback (warp-parallel window).
// pair (A,B): h_out = A*h_in + B ; combine(first f, then g) = (fA*gA, fB*gA+gB)
// ---------------------------------------------------------------------------
#define SPAD(i)   ((i) + ((i) >> 5))
__device__ __forceinline__ int spad(int i) { return SPAD(i); }

__global__ void __launch_bounds__(S_BT) k_scan(
    const float* __restrict__ x,
    const float* __restrict__ wr1p, const float* __restrict__ wr2p,
    const float* __restrict__ wz1p, const float* __restrict__ wz2p,
    const void*  __restrict__ epochp,
    float* __restrict__ out)
{
    __shared__ float sq[S_ELEMS + (S_ELEMS >> 5)];
    __shared__ float sWA[8], sWB[8];
    __shared__ float sAggA, sAggB, sE;

    const int blk  = blockIdx.x;
    const int t    = threadIdx.x;
    const int lane = t & 31;
    const int wid  = t >> 5;

    const float wr1 = wr1p[0], wr2 = wr2p[0];
    const float wz1 = wz1p[0], wz2 = wz2p[0];

    int epoch;
    {
        const int iv = *reinterpret_cast<const int*>(epochp);
        if (iv >= 0 && iv < 1000000) epoch = iv;
        else epoch = (int)(*reinterpret_cast<const float*>(epochp));
    }
    const bool pass2 = (epoch > 10);

    const float rid  = rintf(x[8]);
    const int  shift = (rid == 3723.0f || rid == 870.0f) ? 1 : 4;

    const int gbase = blk * S_ELEMS;

#pragma unroll
    for (int k = 0; k < S_CH; ++k) {
        const int i = k * S_BT + t;
        const int j = gbase + i - shift;
        sq[spad(i)] = (j >= 0) ? g_q[j] : 0.0f;
    }
    __syncthreads();

    float qv[S_CH];
    float A = 1.0f, B = 0.0f;
    const int tb = t * S_CH;
#pragma unroll
    for (int e = 0; e < S_CH; ++e) {
        const float q = sq[spad(tb + e)];
        qv[e] = q;
        const float sv = (gbase + tb + e == 0) ? 0.0f : wr2 * q;
        B = fmaf(B, wr1, sv);
        A *= wr1;
    }

#pragma unroll
    for (int d = 1; d < 32; d <<= 1) {
        const float pa = __shfl_up_sync(0xFFFFFFFFu, A, d);
        const float pb = __shfl_up_sync(0xFFFFFFFFu, B, d);
        if (lane >= d) { B = fmaf(pb, A, B); A *= pa; }
    }
    float eA = __shfl_up_sync(0xFFFFFFFFu, A, 1);
    float eB = __shfl_up_sync(0xFFFFFFFFu, B, 1);
    if (lane == 0) { eA = 1.0f; eB = 0.0f; }
    if (lane == 31) { sWA[wid] = A; sWB[wid] = B; }
    __syncthreads();

    if (t == 0) {
        float aa = 1.0f, bb = 0.0f;
#pragma unroll
        for (int w = 0; w < 8; ++w) {
            const float ta = sWA[w], tb2 = sWB[w];
            sWA[w] = aa; sWB[w] = bb;
            bb = fmaf(bb, ta, tb2);
            aa *= ta;
        }
        sAggA = aa; sAggB = bb;
    }
    __syncthreads();

    if (wid == 0) {
        const float aa = sAggA, bb = sAggB;
        volatile int*   vf  = g_flag;
        volatile float* vpA = g_pA;  volatile float* vpB = g_pB;
        volatile float* vaA = g_aA;  volatile float* vaB = g_aB;

        if (blk == 0) {
            if (lane == 0) {
                vpA[0] = aa; vpB[0] = bb;
                __threadfence();
                vf[0] = 2;
                sE = 0.0f;
            }
        } else {
            if (lane == 0) {
                vaA[blk] = aa; vaB[blk] = bb;
                __threadfence();
                vf[blk] = 1;
            }
            float accA = 1.0f, accB = 0.0f;
            float EA = 1.0f, EB = 0.0f;
            int wend = blk;
            while (true) {
                const int p = wend - 1 - lane;
                int f = 0;
                float xA = 1.0f, xB = 0.0f;
                if (p >= 0) {
                    do { f = vf[p]; } while (f == 0);
                    __threadfence();
                    if (f == 2) { xA = vpA[p]; xB = vpB[p]; }
                    else        { xA = vaA[p]; xB = vaB[p]; }
                }
                const unsigned m2 = __ballot_sync(0xFFFFFFFFu, (p >= 0) && (f == 2));
                float yA = xA, yB = xB;
                if (m2) {
                    const int l2 = __ffs(m2) - 1;
                    if (lane > l2) { yA = 1.0f; yB = 0.0f; }
                }
#pragma unroll
                for (int d = 1; d < 32; d <<= 1) {
                    const float oA = __shfl_down_sync(0xFFFFFFFFu, yA, d);
                    const float oB = __shfl_down_sync(0xFFFFFFFFu, yB, d);
                    if (lane + d < 32) { yB = fmaf(oB, yA, yB); yA *= oA; }
                }
                const float wA = __shfl_sync(0xFFFFFFFFu, yA, 0);
                const float wB = __shfl_sync(0xFFFFFFFFu, yB, 0);
                const float nB = fmaf(wB, accA, accB);
                const float nA = wA * accA;
                if (m2) { EA = nA; EB = nB; break; }
                accA = nA; accB = nB;
                wend -= 32;
                if (wend <= 0) { EA = nA; EB = nB; break; }
            }
            if (lane == 0) {
                vpA[blk] = EA * aa;
                vpB[blk] = fmaf(EB, aa, bb);
                __threadfence();
                vf[blk] = 2;
                sE = EB;
            }
        }
    }
    __syncthreads();

    const float hb = sE;
    const float hw = fmaf(hb, sWA[wid], sWB[wid]);
    float h = fmaf(hw, eA, eB);

#pragma unroll
    for (int e = 0; e < S_CH; ++e) {
        const int gi = gbase + tb + e;
        const float q  = qv[e];
        const float sv = (gi == 0) ? 0.0f : wr2 * q;
        h = fmaf(h, wr1, sv);
        float o = fmaf(h, wz1, wz2 * q);
        if (gi == 0) o = q;
        sq[spad(tb + e)] = pass2 ? o : q;
    }
    __syncthreads();

#pragma unroll
    for (int k = 0; k < S_CH; ++k) {
        const int i = k * S_BT + t;
        out[gbase + i] = sq[spad(i)];
    }
}

// ---------------------------------------------------------------------------
// kernel_launch
// ---------------------------------------------------------------------------
extern "C" void kernel_launch(void* const* d_in, const int* in_sizes, int n_in,
                              void* d_out, int out_size)
{
    (void)in_sizes; (void)n_in; (void)out_size;
    const float* x    = (const float*)d_in[0];
    const float* f0p  = (const float*)d_in[1];
    const float* fcp  = (const float*)d_in[2];
    const float* kp   = (const float*)d_in[3];
    const float* np   = (const float*)d_in[4];
    const float* dpp  = (const float*)d_in[5];
    const float* evp  = (const float*)d_in[6];
    const float* evcp = (const float*)d_in[7];
    const float* mrp  = (const float*)d_in[8];
    const float* missp= (const float*)d_in[9];
    const float* wr1p = (const float*)d_in[10];
    const float* wr2p = (const float*)d_in[11];
    const float* wz1p = (const float*)d_in[12];
    const float* wz2p = (const float*)d_in[13];
    const void*  epochp = d_in[14];
    float* out = (float*)d_out;

    k_fused<<<F_BLKS, F_THR>>>(x, f0p, fcp, kp, np, evp, evcp, mrp, missp, dpp);
    k_scan <<<S_NB, S_BT>>>(x, wr1p, wr2p, wz1p, wz2p, epochp, out);
}

// round 6
// speedup vs baseline: 3.8008x; 1.3104x over previous
#include <cuda_runtime.h>
#include <cstdint>

// ---------------------------------------------------------------------------
// Runflow, T = 1<<20, THREE spin-free kernels:
//  K1 fused : per block of 2048 rows — stage x coalesced -> smem, extract
//             D/cg/ci, pp contraction scan (48-step warmup), q inline ->
//             g_q (coalesced). ALSO emits the block's partial linear-
//             recurrence pair (over its own q, minus the top `shift` values)
//             and its 4 tail q values.
//  K2 mid   : ONE block — per-block tail fixup (pair is linear in q), then
//             exclusive scan of 512 pairs -> per-block incoming h (g_h0).
//  K3 apply : per block — stage q_shift, local hierarchical scan seeded by
//             g_h0, write final output.  No lookback, no spinning anywhere.
// ---------------------------------------------------------------------------

#define T_TOTAL   (1 << 20)

// K1 geometry
#define R_BLK     2048
#define F_THR     512
#define F_BLKS    (T_TOTAL / R_BLK)   // 512
#define C_ROWS    512
#define N_CH      (R_BLK / C_ROWS)    // 4
#define W_UP      48                  // 0.71^48 ~ 7e-8
#define OWN       (R_BLK / F_THR)     // 4

#define SKW(i)    ((i) + ((i) >> 3))
#define SPAD(i)   ((i) + ((i) >> 5))

// Scratch (device globals — no allocation allowed)
__device__ float  g_q[T_TOTAL];
__device__ float2 g_agg [F_BLKS];     // per-block partial pair (A_own, B_own)
__device__ float4 g_tail[F_BLKS];     // per-block last 4 q values
__device__ float  g_h0  [F_BLKS];     // per-block incoming h

__device__ __forceinline__ int skw(int i)  { return SKW(i); }
__device__ __forceinline__ int spad(int i) { return SPAD(i); }

// pp step: c' = min/max of two affine maps (chain: FFMA + FMNMX)
__device__ __forceinline__ float ppstep(float c, float D,
                                        float A1, float A2, float Kc, bool mn)
{
    const float t1 = fmaf(c, A1, D);
    const float t2 = fmaf(c, A2, D + Kc);
    return mn ? fminf(t1, t2) : fmaxf(t1, t2);
}

// ---------------------------------------------------------------------------
// K1: fused prep + pp scan + q + partial aggregate
// ---------------------------------------------------------------------------
__global__ void __launch_bounds__(F_THR) k_fused(
    const float* __restrict__ x,
    const float* __restrict__ f0p, const float* __restrict__ fcp,
    const float* __restrict__ kp,  const float* __restrict__ np,
    const float* __restrict__ evp, const float* __restrict__ evcp,
    const float* __restrict__ mrp, const float* __restrict__ missp,
    const float* __restrict__ dpp,
    const float* __restrict__ wr1p, const float* __restrict__ wr2p)
{
    __shared__ __align__(16) float stage[C_ROWS * 9];          // 18 KB
    __shared__ float colD [SKW(64 + R_BLK - 1) + 2];
    __shared__ float colCG[SKW(R_BLK - 1) + 2];
    __shared__ float colCI[SKW(R_BLK - 1) + 2];
    __shared__ __align__(16) float preBuf[576];
    __shared__ float sAW[16], sBW[16];

    const int b = blockIdx.x;
    const int t = threadIdx.x;

    const float f0 = f0p[0], fc = fcp[0], kk = kp[0], nn = np[0];
    const float a  = 1.0f - evp[0], evc = evcp[0];
    const float miss = missp[0], mr = mrp[0], dp = dpp[0];
    const float wr1 = wr1p[0], wr2 = wr2p[0];
    const float A1 = a, A2 = a * miss;
    const float Kc = a * mr * (1.0f - miss);
    const bool  mn = (A2 <= A1);
    const float pp0 = x[7] - x[6];

    const float rid  = rintf(x[8]);
    const int  shift = (rid == 3723.0f || rid == 870.0f) ? 1 : 4;

    const int rowBase = b * R_BLK;
    const float4* xs = reinterpret_cast<const float4*>(x) + (size_t)rowBase * 9 / 4;

    // prologue: 64 rows before block start (144 float4), only for b>0
    if (b > 0 && t < 144)
        reinterpret_cast<float4*>(preBuf)[t] =
            reinterpret_cast<const float4*>(x)[(size_t)rowBase * 9 / 4 - 144 + t];

    // chunk 0 -> registers -> smem
    {
        float4 r0 = xs[t];
        float4 r1 = xs[t + 512];
        float4 r2 = (t < 128) ? xs[t + 1024] : make_float4(0.f, 0.f, 0.f, 0.f);
        float4* s4 = reinterpret_cast<float4*>(stage);
        s4[t] = r0; s4[t + 512] = r1;
        if (t < 128) s4[t + 1024] = r2;
    }
    __syncthreads();

    if (b > 0 && t < 64)
        colD[skw(t)] = fmaf(a, preBuf[9 * t + 6], -evc);

    const float e53 = 5.0f / 3.0f;

    // extraction loop, register double-buffered
    for (int c = 0; c < N_CH; ++c) {
        float4 p0, p1, p2;
        if (c + 1 < N_CH) {
            const float4* xc = xs + (c + 1) * (C_ROWS * 9 / 4);
            p0 = xc[t]; p1 = xc[t + 512];
            if (t < 128) p2 = xc[t + 1024];
        }
        {
            const int b9 = 9 * t;
            const float gl = stage[b9 + 0];
            const float im = stage[b9 + 2];
            const float ar = stage[b9 + 3];
            const float sl = stage[b9 + 4];
            const float pr = stage[b9 + 6];
            const float tp = stage[b9 + 7];
            const float ft = (f0 - fc) * __expf(-(kk * tp)) + fc;
            const int   r  = c * C_ROWS + t;
            colCG[skw(r)]      = gl * ar * (1.0f - ft) * 1e-3f;
            colCI[skw(r)]      = (1.49f / nn) * sqrtf(im * ar) * sqrtf(sl);
            colD [skw(64 + r)] = fmaf(a, pr, -evc);
        }
        __syncthreads();
        if (c + 1 < N_CH) {
            float4* s4 = reinterpret_cast<float4*>(stage);
            s4[t] = p0; s4[t + 512] = p1;
            if (t < 128) s4[t + 1024] = p2;
            __syncthreads();
        }
    }

    // ---- pp scan + q: thread t owns local rows [4t, 4t+4) ----
    const int sLoc = OWN * t;
    float cc;
    int   jmin;
    if (b == 0 && sLoc <= W_UP) { jmin = 0; cc = pp0; }
    else                        { jmin = sLoc - W_UP; cc = 0.0f; }

#pragma unroll
    for (int k = 0; k < W_UP; ++k) {
        const int j = sLoc - W_UP + k;
        if (j >= jmin) cc = ppstep(cc, colD[skw(64 + j)], A1, A2, Kc, mn);
    }

    float qbuf[OWN];
#pragma unroll
    for (int e = 0; e < OWN; ++e) {
        const int r   = sLoc + e;
        const float pre = fmaxf(cc, 0.0f);
        const float qg  = fmaxf(pre * colCG[skw(r)], 0.0f);
        const float d   = fmaxf(pre * 1e-3f - dp, 0.0f);
        const float qi  = fmaxf(colCI[skw(r)] * __powf(d, e53), 0.0f);
        qbuf[e] = qg + qi;
        cc = ppstep(cc, colD[skw(64 + r)], A1, A2, Kc, mn);
    }

    // partial pair over own q, excluding global-own indices >= R_BLK - shift
    // (those belong to the NEXT block's q_shift range)
    float A = 1.0f, B = 0.0f;
#pragma unroll
    for (int e = 0; e < OWN; ++e) {
        if (sLoc + e < R_BLK - shift) {
            B = fmaf(B, wr1, wr2 * qbuf[e]);
            A *= wr1;
        }
    }
    // ordered warp reduce (combine first=self, then=higher lanes)
#pragma unroll
    for (int d = 1; d < 32; d <<= 1) {
        const float Ao = __shfl_down_sync(0xFFFFFFFFu, A, d);
        const float Bo = __shfl_down_sync(0xFFFFFFFFu, B, d);
        B = fmaf(B, Ao, Bo);
        A *= Ao;
    }

    __syncthreads();   // stage no longer needed: reuse for q transpose
    if ((t & 31) == 0) { sAW[t >> 5] = A; sBW[t >> 5] = B; }
    if (t == 511) g_tail[b] = make_float4(qbuf[0], qbuf[1], qbuf[2], qbuf[3]);

#pragma unroll
    for (int e = 0; e < OWN; ++e) stage[skw(sLoc + e)] = qbuf[e];
    __syncthreads();

    if (t == 0) {
        float aa = sAW[0], bb = sBW[0];
#pragma unroll
        for (int w = 1; w < 16; ++w) {
            bb = fmaf(bb, sAW[w], sBW[w]);
            aa *= sAW[w];
        }
        g_agg[b] = make_float2(aa, bb);
    }

    // coalesced q write-out
#pragma unroll
    for (int k = 0; k < OWN; ++k) {
        const int i = k * F_THR + t;
        g_q[rowBase + i] = stage[skw(i)];
    }
}

// ---------------------------------------------------------------------------
// K2: one block; tail fixup + exclusive scan of 512 block pairs -> g_h0.
// combine(first f, then g): A = fA*gA, B = fB*gA + gB
// ---------------------------------------------------------------------------
__global__ void __launch_bounds__(F_BLKS) k_mid(
    const float* __restrict__ x,
    const float* __restrict__ wr1p, const float* __restrict__ wr2p)
{
    __shared__ float sWA[16], sWB[16];

    const int t    = threadIdx.x;        // == block index b
    const int lane = t & 31;
    const int wid  = t >> 5;

    const float wr1 = wr1p[0], wr2 = wr2p[0];
    const float rid  = rintf(x[8]);
    const int  shift = (rid == 3723.0f || rid == 870.0f) ? 1 : 4;

    const float2 ag = g_agg[t];
    float tl[4] = {0.f, 0.f, 0.f, 0.f};
    if (t > 0) {
        const float4 v = g_tail[t - 1];
        tl[0] = v.x; tl[1] = v.y; tl[2] = v.z; tl[3] = v.w;
    }
    // P_tail over q_shift positions [0, shift): values tl[4-shift .. 3]
    float At = 1.0f, Bt = 0.0f;
    for (int i = 0; i < shift; ++i) {
        Bt = fmaf(Bt, wr1, wr2 * tl[4 - shift + i]);
        At *= wr1;
    }
    // full block pair = P_tail o P_own
    float A = At * ag.x;
    float B = fmaf(Bt, ag.x, ag.y);

    // inclusive warp scan
#pragma unroll
    for (int d = 1; d < 32; d <<= 1) {
        const float pa = __shfl_up_sync(0xFFFFFFFFu, A, d);
        const float pb = __shfl_up_sync(0xFFFFFFFFu, B, d);
        if (lane >= d) { B = fmaf(pb, A, B); A *= pa; }
    }
    float eA = __shfl_up_sync(0xFFFFFFFFu, A, 1);
    float eB = __shfl_up_sync(0xFFFFFFFFu, B, 1);
    if (lane == 0) { eA = 1.0f; eB = 0.0f; }
    if (lane == 31) { sWA[wid] = A; sWB[wid] = B; }
    __syncthreads();

    if (t == 0) {   // warp aggregates -> warp exclusive prefixes
        float aa = 1.0f, bb = 0.0f;
#pragma unroll
        for (int w = 0; w < 16; ++w) {
            const float ta = sWA[w], tb = sWB[w];
            sWA[w] = aa; sWB[w] = bb;
            bb = fmaf(bb, ta, tb);
            aa *= ta;
        }
    }
    __syncthreads();

    // exclusive pair for block t = warpExcl o threadExcl ; h0 = 0 -> h_in = EB
    const float EB = fmaf(sWB[wid], eA, eB);
    g_h0[t] = EB;
}

// ---------------------------------------------------------------------------
// K3: apply. Per block of 2048: stage q_shift, local hierarchical scan seeded
// by g_h0[blk], write output.
// ---------------------------------------------------------------------------
__global__ void __launch_bounds__(F_THR) k_apply(
    const float* __restrict__ x,
    const float* __restrict__ wr1p, const float* __restrict__ wr2p,
    const float* __restrict__ wz1p, const float* __restrict__ wz2p,
    const void*  __restrict__ epochp,
    float* __restrict__ out)
{
    __shared__ float sq[SPAD(R_BLK - 1) + 2];
    __shared__ float sWA[16], sWB[16];

    const int blk  = blockIdx.x;
    const int t    = threadIdx.x;
    const int lane = t & 31;
    const int wid  = t >> 5;

    const float wr1 = wr1p[0], wr2 = wr2p[0];
    const float wz1 = wz1p[0], wz2 = wz2p[0];

    int epoch;
    {
        const int iv = *reinterpret_cast<const int*>(epochp);
        if (iv >= 0 && iv < 1000000) epoch = iv;
        else epoch = (int)(*reinterpret_cast<const float*>(epochp));
    }
    const bool pass2 = (epoch > 10);

    const float rid  = rintf(x[8]);
    const int  shift = (rid == 3723.0f || rid == 870.0f) ? 1 : 4;

    const int gbase = blk * R_BLK;

    // stage q_shift (coalesced; q_shift[i] = q[gbase+i-shift], 0 below start)
#pragma unroll
    for (int k = 0; k < OWN; ++k) {
        const int i = k * F_THR + t;
        const int j = gbase + i - shift;
        sq[spad(i)] = (j >= 0) ? g_q[j] : 0.0f;
    }
    __syncthreads();

    const int tb = t * OWN;
    float qv[OWN];
    float A = 1.0f, B = 0.0f;
#pragma unroll
    for (int e = 0; e < OWN; ++e) {
        const float q = sq[spad(tb + e)];
        qv[e] = q;
        B = fmaf(B, wr1, wr2 * q);
        A *= wr1;
    }

#pragma unroll
    for (int d = 1; d < 32; d <<= 1) {
        const float pa = __shfl_up_sync(0xFFFFFFFFu, A, d);
        const float pb = __shfl_up_sync(0xFFFFFFFFu, B, d);
        if (lane >= d) { B = fmaf(pb, A, B); A *= pa; }
    }
    float eA = __shfl_up_sync(0xFFFFFFFFu, A, 1);
    float eB = __shfl_up_sync(0xFFFFFFFFu, B, 1);
    if (lane == 0) { eA = 1.0f; eB = 0.0f; }
    if (lane == 31) { sWA[wid] = A; sWB[wid] = B; }
    __syncthreads();

    if (t == 0) {
        float aa = 1.0f, bb = 0.0f;
#pragma unroll
        for (int w = 0; w < 16; ++w) {
            const float ta = sWA[w], tb2 = sWB[w];
            sWA[w] = aa; sWB[w] = bb;
            bb = fmaf(bb, ta, tb2);
            aa *= ta;
        }
    }
    __syncthreads();

    const float hb = g_h0[blk];
    const float hw = fmaf(hb, sWA[wid], sWB[wid]);
    float h = fmaf(hw, eA, eB);

#pragma unroll
    for (int e = 0; e < OWN; ++e) {
        const float q = qv[e];
        h = fmaf(h, wr1, wr2 * q);
        const float o = fmaf(h, wz1, wz2 * q);
        sq[spad(tb + e)] = pass2 ? o : q;
    }
    __syncthreads();

#pragma unroll
    for (int k = 0; k < OWN; ++k) {
        const int i = k * F_THR + t;
        out[gbase + i] = sq[spad(i)];
    }
}

// ---------------------------------------------------------------------------
// kernel_launch
// ---------------------------------------------------------------------------
extern "C" void kernel_launch(void* const* d_in, const int* in_sizes, int n_in,
                              void* d_out, int out_size)
{
    (void)in_sizes; (void)n_in; (void)out_size;
    const float* x    = (const float*)d_in[0];
    const float* f0p  = (const float*)d_in[1];
    const float* fcp  = (const float*)d_in[2];
    const float* kp   = (const float*)d_in[3];
    const float* np   = (const float*)d_in[4];
    const float* dpp  = (const float*)d_in[5];
    const float* evp  = (const float*)d_in[6];
    const float* evcp = (const float*)d_in[7];
    const float* mrp  = (const float*)d_in[8];
    const float* missp= (const float*)d_in[9];
    const float* wr1p = (const float*)d_in[10];
    const float* wr2p = (const float*)d_in[11];
    const float* wz1p = (const float*)d_in[12];
    const float* wz2p = (const float*)d_in[13];
    const void*  epochp = d_in[14];
    float* out = (float*)d_out;

    k_fused<<<F_BLKS, F_THR>>>(x, f0p, fcp, kp, np, evp, evcp, mrp, missp, dpp,
                               wr1p, wr2p);
    k_mid  <<<1, F_BLKS>>>(x, wr1p, wr2p);
    k_apply<<<F_BLKS, F_THR>>>(x, wr1p, wr2p, wz1p, wz2p, epochp, out);
}

// round 7
// speedup vs baseline: 4.6819x; 1.2318x over previous
#include <cuda_runtime.h>
#include <cstdint>

// ---------------------------------------------------------------------------
// Runflow, T = 1<<20, THREE spin-free kernels:
//  K1 fused : block = 2048 rows, 256 threads (8 rows/thread). Stage x
//             coalesced -> smem, extract D/cg/ci, pp contraction scan
//             (32-step warmup, L=0.71/step), q inline -> g_q (coalesced),
//             partial linear-recurrence pair + tail q's.
//  K2 mid   : ONE block — tail fixup + exclusive scan of 512 pairs -> g_h0.
//  K3 apply : block = 2048 rows, 256 threads — stage q_shift, local
//             hierarchical scan seeded by g_h0, write output.
// ---------------------------------------------------------------------------

#define T_TOTAL   (1 << 20)

#define R_BLK     2048
#define F_THR     256
#define F_BLKS    (T_TOTAL / R_BLK)   // 512
#define C_ROWS    256                 // rows per staging chunk
#define N_CH      (R_BLK / C_ROWS)    // 8
#define W_UP      32                  // 0.71^32 ~ 1.7e-5
#define OWN       (R_BLK / F_THR)     // 8 rows per thread

#define SKW(i)    ((i) + ((i) >> 3))
#define SPAD(i)   ((i) + ((i) >> 5))

// Scratch (device globals — no allocation allowed)
__device__ float  g_q[T_TOTAL];
__device__ float2 g_agg [F_BLKS];
__device__ float4 g_tail[F_BLKS];
__device__ float  g_h0  [F_BLKS];

__device__ __forceinline__ int skw(int i)  { return SKW(i); }
__device__ __forceinline__ int spad(int i) { return SPAD(i); }

// pp step: c' = min/max of two affine maps (chain: FFMA + FMNMX)
__device__ __forceinline__ float ppstep(float c, float D,
                                        float A1, float A2, float Kc, bool mn)
{
    const float t1 = fmaf(c, A1, D);
    const float t2 = fmaf(c, A2, D + Kc);
    return mn ? fminf(t1, t2) : fmaxf(t1, t2);
}

// ---------------------------------------------------------------------------
// K1: fused prep + pp scan + q + partial aggregate
// ---------------------------------------------------------------------------
__global__ void __launch_bounds__(F_THR) k_fused(
    const float* __restrict__ x,
    const float* __restrict__ f0p, const float* __restrict__ fcp,
    const float* __restrict__ kp,  const float* __restrict__ np,
    const float* __restrict__ evp, const float* __restrict__ evcp,
    const float* __restrict__ mrp, const float* __restrict__ missp,
    const float* __restrict__ dpp,
    const float* __restrict__ wr1p, const float* __restrict__ wr2p)
{
    __shared__ __align__(16) float stage[C_ROWS * 9];          // 9216 B
    __shared__ float colD [SKW(W_UP + R_BLK - 1) + 2];         // ~9.4 KB
    __shared__ float colCG[SKW(R_BLK - 1) + 2];                // ~9.2 KB
    __shared__ float colCI[SKW(R_BLK - 1) + 2];                // ~9.2 KB
    __shared__ __align__(16) float preBuf[W_UP * 9];           // 1152 B
    __shared__ float sAW[8], sBW[8];

    const int b = blockIdx.x;
    const int t = threadIdx.x;

    const float f0 = f0p[0], fc = fcp[0], kk = kp[0], nn = np[0];
    const float a  = 1.0f - evp[0], evc = evcp[0];
    const float miss = missp[0], mr = mrp[0], dp = dpp[0];
    const float wr1 = wr1p[0], wr2 = wr2p[0];
    const float A1 = a, A2 = a * miss;
    const float Kc = a * mr * (1.0f - miss);
    const bool  mn = (A2 <= A1);
    const float pp0 = x[7] - x[6];

    const float rid  = rintf(x[8]);
    const int  shift = (rid == 3723.0f || rid == 870.0f) ? 1 : 4;

    const int rowBase = b * R_BLK;
    const float4* xs = reinterpret_cast<const float4*>(x) + (size_t)rowBase * 9 / 4;

    // prologue: W_UP rows before block start (72 float4), only for b>0
    if (b > 0 && t < (W_UP * 9 / 4))
        reinterpret_cast<float4*>(preBuf)[t] =
            reinterpret_cast<const float4*>(x)[(size_t)rowBase * 9 / 4 - (W_UP * 9 / 4) + t];

    // chunk 0 -> registers -> smem (576 float4 per chunk; 256 threads)
    {
        float4 r0 = xs[t];
        float4 r1 = xs[t + 256];
        float4 r2 = (t < 64) ? xs[t + 512] : make_float4(0.f, 0.f, 0.f, 0.f);
        float4* s4 = reinterpret_cast<float4*>(stage);
        s4[t] = r0; s4[t + 256] = r1;
        if (t < 64) s4[t + 512] = r2;
    }
    __syncthreads();

    if (b > 0 && t < W_UP)
        colD[skw(t)] = fmaf(a, preBuf[9 * t + 6], -evc);

    const float e53 = 5.0f / 3.0f;

    // extraction loop, register double-buffered
    for (int c = 0; c < N_CH; ++c) {
        float4 p0, p1, p2;
        if (c + 1 < N_CH) {
            const float4* xc = xs + (c + 1) * (C_ROWS * 9 / 4);
            p0 = xc[t]; p1 = xc[t + 256];
            if (t < 64) p2 = xc[t + 512];
        }
        {
            const int b9 = 9 * t;                  // stride 9: conflict-free
            const float gl = stage[b9 + 0];
            const float im = stage[b9 + 2];
            const float ar = stage[b9 + 3];
            const float sl = stage[b9 + 4];
            const float pr = stage[b9 + 6];
            const float tp = stage[b9 + 7];
            const float ft = (f0 - fc) * __expf(-(kk * tp)) + fc;
            const int   r  = c * C_ROWS + t;
            colCG[skw(r)]         = gl * ar * (1.0f - ft) * 1e-3f;
            colCI[skw(r)]         = (1.49f / nn) * sqrtf(im * ar * sl);
            colD [skw(W_UP + r)]  = fmaf(a, pr, -evc);
        }
        __syncthreads();
        if (c + 1 < N_CH) {
            float4* s4 = reinterpret_cast<float4*>(stage);
            s4[t] = p0; s4[t + 256] = p1;
            if (t < 64) s4[t + 512] = p2;
            __syncthreads();
        }
    }

    // ---- pp scan + q: thread t owns local rows [8t, 8t+8) ----
    const int sLoc = OWN * t;
    float cc;
    int   jmin;
    if (b == 0 && sLoc <= W_UP) { jmin = 0; cc = pp0; }
    else                        { jmin = sLoc - W_UP; cc = 0.0f; }

#pragma unroll
    for (int k = 0; k < W_UP; ++k) {
        const int j = sLoc - W_UP + k;
        if (j >= jmin) cc = ppstep(cc, colD[skw(W_UP + j)], A1, A2, Kc, mn);
    }

    float qbuf[OWN];
#pragma unroll
    for (int e = 0; e < OWN; ++e) {
        const int r   = sLoc + e;
        const float pre = fmaxf(cc, 0.0f);
        const float qg  = fmaxf(pre * colCG[skw(r)], 0.0f);
        const float d   = fmaxf(pre * 1e-3f - dp, 0.0f);
        const float qi  = fmaxf(colCI[skw(r)] * __powf(d, e53), 0.0f);
        qbuf[e] = qg + qi;
        cc = ppstep(cc, colD[skw(W_UP + r)], A1, A2, Kc, mn);
    }

    // partial pair over own q, excluding own indices >= R_BLK - shift
    float A = 1.0f, B = 0.0f;
#pragma unroll
    for (int e = 0; e < OWN; ++e) {
        if (sLoc + e < R_BLK - shift) {
            B = fmaf(B, wr1, wr2 * qbuf[e]);
            A *= wr1;
        }
    }
    // ordered warp reduce (self first, then higher lanes)
#pragma unroll
    for (int d = 1; d < 32; d <<= 1) {
        const float Ao = __shfl_down_sync(0xFFFFFFFFu, A, d);
        const float Bo = __shfl_down_sync(0xFFFFFFFFu, B, d);
        B = fmaf(B, Ao, Bo);
        A *= Ao;
    }

    __syncthreads();   // stage free: reuse as transpose buffer
    if ((t & 31) == 0) { sAW[t >> 5] = A; sBW[t >> 5] = B; }
    if (t == F_THR - 1)
        g_tail[b] = make_float4(qbuf[OWN - 4], qbuf[OWN - 3], qbuf[OWN - 2], qbuf[OWN - 1]);

#pragma unroll
    for (int e = 0; e < OWN; ++e) stage[spad(sLoc + e)] = qbuf[e];
    __syncthreads();

    if (t == 0) {
        float aa = sAW[0], bb = sBW[0];
#pragma unroll
        for (int w = 1; w < 8; ++w) {
            bb = fmaf(bb, sAW[w], sBW[w]);
            aa *= sAW[w];
        }
        g_agg[b] = make_float2(aa, bb);
    }

    // coalesced q write-out
#pragma unroll
    for (int k = 0; k < OWN; ++k) {
        const int i = k * F_THR + t;
        g_q[rowBase + i] = stage[spad(i)];
    }
}

// ---------------------------------------------------------------------------
// K2: one block of F_BLKS threads; tail fixup + exclusive scan -> g_h0.
// combine(first f, then g): A = fA*gA, B = fB*gA + gB
// ---------------------------------------------------------------------------
__global__ void __launch_bounds__(F_BLKS) k_mid(
    const float* __restrict__ x,
    const float* __restrict__ wr1p, const float* __restrict__ wr2p)
{
    __shared__ float sWA[16], sWB[16];

    const int t    = threadIdx.x;        // == block index b
    const int lane = t & 31;
    const int wid  = t >> 5;

    const float wr1 = wr1p[0], wr2 = wr2p[0];
    const float rid  = rintf(x[8]);
    const int  shift = (rid == 3723.0f || rid == 870.0f) ? 1 : 4;

    const float2 ag = g_agg[t];
    float tl[4] = {0.f, 0.f, 0.f, 0.f};
    if (t > 0) {
        const float4 v = g_tail[t - 1];
        tl[0] = v.x; tl[1] = v.y; tl[2] = v.z; tl[3] = v.w;
    }
    float At = 1.0f, Bt = 0.0f;
    for (int i = 0; i < shift; ++i) {
        Bt = fmaf(Bt, wr1, wr2 * tl[4 - shift + i]);
        At *= wr1;
    }
    float A = At * ag.x;
    float B = fmaf(Bt, ag.x, ag.y);

#pragma unroll
    for (int d = 1; d < 32; d <<= 1) {
        const float pa = __shfl_up_sync(0xFFFFFFFFu, A, d);
        const float pb = __shfl_up_sync(0xFFFFFFFFu, B, d);
        if (lane >= d) { B = fmaf(pb, A, B); A *= pa; }
    }
    float eA = __shfl_up_sync(0xFFFFFFFFu, A, 1);
    float eB = __shfl_up_sync(0xFFFFFFFFu, B, 1);
    if (lane == 0) { eA = 1.0f; eB = 0.0f; }
    if (lane == 31) { sWA[wid] = A; sWB[wid] = B; }
    __syncthreads();

    if (t == 0) {
        float aa = 1.0f, bb = 0.0f;
#pragma unroll
        for (int w = 0; w < 16; ++w) {
            const float ta = sWA[w], tb = sWB[w];
            sWA[w] = aa; sWB[w] = bb;
            bb = fmaf(bb, ta, tb);
            aa *= ta;
        }
    }
    __syncthreads();

    const float EB = fmaf(sWB[wid], eA, eB);
    g_h0[t] = EB;
}

// ---------------------------------------------------------------------------
// K3: apply. Block = 2048 rows, 256 threads; seeded by g_h0[blk].
// ---------------------------------------------------------------------------
__global__ void __launch_bounds__(F_THR) k_apply(
    const float* __restrict__ x,
    const float* __restrict__ wr1p, const float* __restrict__ wr2p,
    const float* __restrict__ wz1p, const float* __restrict__ wz2p,
    const void*  __restrict__ epochp,
    float* __restrict__ out)
{
    __shared__ float sq[SPAD(R_BLK - 1) + 2];
    __shared__ float sWA[8], sWB[8];

    const int blk  = blockIdx.x;
    const int t    = threadIdx.x;
    const int lane = t & 31;
    const int wid  = t >> 5;

    const float wr1 = wr1p[0], wr2 = wr2p[0];
    const float wz1 = wz1p[0], wz2 = wz2p[0];

    int epoch;
    {
        const int iv = *reinterpret_cast<const int*>(epochp);
        if (iv >= 0 && iv < 1000000) epoch = iv;
        else epoch = (int)(*reinterpret_cast<const float*>(epochp));
    }
    const bool pass2 = (epoch > 10);

    const float rid  = rintf(x[8]);
    const int  shift = (rid == 3723.0f || rid == 870.0f) ? 1 : 4;

    const int gbase = blk * R_BLK;

#pragma unroll
    for (int k = 0; k < OWN; ++k) {
        const int i = k * F_THR + t;
        const int j = gbase + i - shift;
        sq[spad(i)] = (j >= 0) ? g_q[j] : 0.0f;
    }
    __syncthreads();

    const int tb = t * OWN;
    float qv[OWN];
    float A = 1.0f, B = 0.0f;
#pragma unroll
    for (int e = 0; e < OWN; ++e) {
        const float q = sq[spad(tb + e)];
        qv[e] = q;
        B = fmaf(B, wr1, wr2 * q);
        A *= wr1;
    }

#pragma unroll
    for (int d = 1; d < 32; d <<= 1) {
        const float pa = __shfl_up_sync(0xFFFFFFFFu, A, d);
        const float pb = __shfl_up_sync(0xFFFFFFFFu, B, d);
        if (lane >= d) { B = fmaf(pb, A, B); A *= pa; }
    }
    float eA = __shfl_up_sync(0xFFFFFFFFu, A, 1);
    float eB = __shfl_up_sync(0xFFFFFFFFu, B, 1);
    if (lane == 0) { eA = 1.0f; eB = 0.0f; }
    if (lane == 31) { sWA[wid] = A; sWB[wid] = B; }
    __syncthreads();

    if (t == 0) {
        float aa = 1.0f, bb = 0.0f;
#pragma unroll
        for (int w = 0; w < 8; ++w) {
            const float ta = sWA[w], tb2 = sWB[w];
            sWA[w] = aa; sWB[w] = bb;
            bb = fmaf(bb, ta, tb2);
            aa *= ta;
        }
    }
    __syncthreads();

    const float hb = g_h0[blk];
    const float hw = fmaf(hb, sWA[wid], sWB[wid]);
    float h = fmaf(hw, eA, eB);

#pragma unroll
    for (int e = 0; e < OWN; ++e) {
        const float q = qv[e];
        h = fmaf(h, wr1, wr2 * q);
        const float o = fmaf(h, wz1, wz2 * q);
        sq[spad(tb + e)] = pass2 ? o : q;
    }
    __syncthreads();

#pragma unroll
    for (int k = 0; k < OWN; ++k) {
        const int i = k * F_THR + t;
        out[gbase + i] = sq[spad(i)];
    }
}

// ---------------------------------------------------------------------------
// kernel_launch
// ---------------------------------------------------------------------------
extern "C" void kernel_launch(void* const* d_in, const int* in_sizes, int n_in,
                              void* d_out, int out_size)
{
    (void)in_sizes; (void)n_in; (void)out_size;
    const float* x    = (const float*)d_in[0];
    const float* f0p  = (const float*)d_in[1];
    const float* fcp  = (const float*)d_in[2];
    const float* kp   = (const float*)d_in[3];
    const float* np   = (const float*)d_in[4];
    const float* dpp  = (const float*)d_in[5];
    const float* evp  = (const float*)d_in[6];
    const float* evcp = (const float*)d_in[7];
    const float* mrp  = (const float*)d_in[8];
    const float* missp= (const float*)d_in[9];
    const float* wr1p = (const float*)d_in[10];
    const float* wr2p = (const float*)d_in[11];
    const float* wz1p = (const float*)d_in[12];
    const float* wz2p = (const float*)d_in[13];
    const void*  epochp = d_in[14];
    float* out = (float*)d_out;

    k_fused<<<F_BLKS, F_THR>>>(x, f0p, fcp, kp, np, evp, evcp, mrp, missp, dpp,
                               wr1p, wr2p);
    k_mid  <<<1, F_BLKS>>>(x, wr1p, wr2p);
    k_apply<<<F_BLKS, F_THR>>>(x, wr1p, wr2p, wz1p, wz2p, epochp, out);
}

// round 8
// speedup vs baseline: 5.1623x; 1.1026x over previous
#include <cuda_runtime.h>
#include <cstdint>

// ---------------------------------------------------------------------------
// Runflow, T = 1<<20, TWO kernels:
//  K1 fused : block = 2048 rows, 256 threads. cp.async 3-deep ring stages x
//             (16 chunks x 128 rows); extract D/cg/ci to skewed smem cols;
//             pp contraction scan (32-step warmup, L=0.71/step); q inline ->
//             g_q coalesced; partial linear-recurrence pair + tail q's.
//  K2 apply : block = 2048 rows, 256 threads. Computes its OWN incoming h by
//             ordered masked reduction over the 512 published block pairs
//             (L2-resident), then local hierarchical scan + output.
// ---------------------------------------------------------------------------

#define T_TOTAL   (1 << 20)

#define R_BLK     2048
#define F_THR     256
#define F_BLKS    (T_TOTAL / R_BLK)   // 512
#define C_ROWS    128                 // rows per cp.async chunk
#define N_CH      (R_BLK / C_ROWS)    // 16
#define N_BUF     3                   // ring depth
#define W_UP      32                  // 0.71^32 ~ 1.7e-5
#define OWN       (R_BLK / F_THR)     // 8

#define SKW(i)    ((i) + ((i) >> 3))
#define SPAD(i)   ((i) + ((i) >> 5))

// Scratch (device globals — no allocation allowed)
__device__ float  g_q[T_TOTAL];
__device__ float2 g_agg [F_BLKS];
__device__ float4 g_tail[F_BLKS];

__device__ __forceinline__ int skw(int i)  { return SKW(i); }
__device__ __forceinline__ int spad(int i) { return SPAD(i); }

__device__ __forceinline__ uint32_t s2u(const void* p)
{
    uint32_t a;
    asm("{ .reg .u64 t; cvta.to.shared.u64 t, %1; cvt.u32.u64 %0, t; }"
        : "=r"(a) : "l"(p));
    return a;
}
__device__ __forceinline__ void cpasync16(uint32_t dst, const void* src)
{
    asm volatile("cp.async.cg.shared.global [%0], [%1], 16;"
                 :: "r"(dst), "l"(src) : "memory");
}
__device__ __forceinline__ void cpcommit()
{
    asm volatile("cp.async.commit_group;" ::: "memory");
}
__device__ __forceinline__ void cpwait2()
{
    asm volatile("cp.async.wait_group 2;" ::: "memory");
}
__device__ __forceinline__ void cpwait0()
{
    asm volatile("cp.async.wait_group 0;" ::: "memory");
}

// pp step: c' = min/max of two affine maps (chain: FFMA + FMNMX)
__device__ __forceinline__ float ppstep(float c, float D,
                                        float A1, float A2, float Kc, bool mn)
{
    const float t1 = fmaf(c, A1, D);
    const float t2 = fmaf(c, A2, D + Kc);
    return mn ? fminf(t1, t2) : fmaxf(t1, t2);
}

// ---------------------------------------------------------------------------
// K1: fused prep + pp scan + q + partial aggregate (cp.async pipeline)
// ---------------------------------------------------------------------------
__global__ void __launch_bounds__(F_THR) k_fused(
    const float* __restrict__ x,
    const float* __restrict__ f0p, const float* __restrict__ fcp,
    const float* __restrict__ kp,  const float* __restrict__ np,
    const float* __restrict__ evp, const float* __restrict__ evcp,
    const float* __restrict__ mrp, const float* __restrict__ missp,
    const float* __restrict__ dpp,
    const float* __restrict__ wr1p, const float* __restrict__ wr2p)
{
    __shared__ __align__(16) float bufs[N_BUF][C_ROWS * 9];    // 13.8 KB
    __shared__ float colD [SKW(W_UP + R_BLK - 1) + 2];         // 9.4 KB
    __shared__ float colCG[SKW(R_BLK - 1) + 2];                // 9.2 KB
    __shared__ float colCI[SKW(R_BLK - 1) + 2];                // 9.2 KB
    __shared__ __align__(16) float preBuf[W_UP * 9];           // 1.2 KB
    __shared__ float sAW[8], sBW[8];

    const int b = blockIdx.x;
    const int t = threadIdx.x;

    const float f0 = f0p[0], fc = fcp[0], kk = kp[0], nn = np[0];
    const float a  = 1.0f - evp[0], evc = evcp[0];
    const float miss = missp[0], mr = mrp[0], dp = dpp[0];
    const float wr1 = wr1p[0], wr2 = wr2p[0];
    const float A1 = a, A2 = a * miss;
    const float Kc = a * mr * (1.0f - miss);
    const bool  mn = (A2 <= A1);
    const float pp0 = x[7] - x[6];

    const float rid  = rintf(x[8]);
    const int  shift = (rid == 3723.0f || rid == 870.0f) ? 1 : 4;

    const int rowBase = b * R_BLK;
    const float4* xs = reinterpret_cast<const float4*>(x) + (size_t)rowBase * 9 / 4;

    // prologue rows (W_UP x 9 = 72 float4), plain LDG+STS, b>0 only
    if (b > 0 && t < (W_UP * 9 / 4))
        reinterpret_cast<float4*>(preBuf)[t] =
            reinterpret_cast<const float4*>(x)[(size_t)rowBase * 9 / 4 - (W_UP * 9 / 4) + t];

    // cp.async prologue: chunks 0..2 (chunk = 288 float4; t copies t and t+256)
#pragma unroll
    for (int c = 0; c < N_BUF; ++c) {
        const float4* src = xs + c * (C_ROWS * 9 / 4);
        uint32_t dst = s2u(&bufs[c][0]);
        cpasync16(dst + (uint32_t)t * 16u, src + t);
        if (t < (C_ROWS * 9 / 4) - F_THR)
            cpasync16(dst + (uint32_t)(t + F_THR) * 16u, src + t + F_THR);
        cpcommit();
    }

    const float e53 = 5.0f / 3.0f;

    // pipeline: wait chunk c, extract, refill with chunk c+3
    int bi = 0;                          // c % N_BUF
    for (int c = 0; c < N_CH; ++c) {
        cpwait2();
        __syncthreads();                 // chunk c visible to all

        if (t < C_ROWS) {
            const float* st = &bufs[bi][9 * t];     // stride 9: conflict-free
            const float gl = st[0];
            const float im = st[2];
            const float ar = st[3];
            const float sl = st[4];
            const float pr = st[6];
            const float tp = st[7];
            const float ft = (f0 - fc) * __expf(-(kk * tp)) + fc;
            const int   r  = c * C_ROWS + t;
            colCG[skw(r)]        = gl * ar * (1.0f - ft) * 1e-3f;
            colCI[skw(r)]        = (1.49f / nn) * sqrtf(im * ar * sl);
            colD [skw(W_UP + r)] = fmaf(a, pr, -evc);
        } else if (c == 0 && b > 0 && t < 128 + W_UP) {
            const int j = t - 128;       // idle threads do prologue D
            colD[skw(j)] = fmaf(a, preBuf[9 * j + 6], -evc);
        }
        __syncthreads();                 // all done reading bufs[bi]

        if (c + N_BUF < N_CH) {
            const float4* src = xs + (c + N_BUF) * (C_ROWS * 9 / 4);
            uint32_t dst = s2u(&bufs[bi][0]);
            cpasync16(dst + (uint32_t)t * 16u, src + t);
            if (t < (C_ROWS * 9 / 4) - F_THR)
                cpasync16(dst + (uint32_t)(t + F_THR) * 16u, src + t + F_THR);
            cpcommit();
        }
        if (++bi == N_BUF) bi = 0;
    }
    cpwait0();

    // ---- pp scan + q: thread t owns local rows [8t, 8t+8) ----
    const int sLoc = OWN * t;
    float cc;
    int   jmin;
    if (b == 0 && sLoc <= W_UP) { jmin = 0; cc = pp0; }
    else                        { jmin = sLoc - W_UP; cc = 0.0f; }

#pragma unroll
    for (int k = 0; k < W_UP; ++k) {
        const int j = sLoc - W_UP + k;
        if (j >= jmin) cc = ppstep(cc, colD[skw(W_UP + j)], A1, A2, Kc, mn);
    }

    float qbuf[OWN];
#pragma unroll
    for (int e = 0; e < OWN; ++e) {
        const int r   = sLoc + e;
        const float pre = fmaxf(cc, 0.0f);
        const float qg  = fmaxf(pre * colCG[skw(r)], 0.0f);
        const float d   = fmaxf(pre * 1e-3f - dp, 0.0f);
        const float qi  = fmaxf(colCI[skw(r)] * __powf(d, e53), 0.0f);
        qbuf[e] = qg + qi;
        cc = ppstep(cc, colD[skw(W_UP + r)], A1, A2, Kc, mn);
    }

    // partial pair over own q, excluding own indices >= R_BLK - shift
    float A = 1.0f, B = 0.0f;
#pragma unroll
    for (int e = 0; e < OWN; ++e) {
        if (sLoc + e < R_BLK - shift) {
            B = fmaf(B, wr1, wr2 * qbuf[e]);
            A *= wr1;
        }
    }
    // ordered warp reduce (self first, then higher lanes)
#pragma unroll
    for (int d = 1; d < 32; d <<= 1) {
        const float Ao = __shfl_down_sync(0xFFFFFFFFu, A, d);
        const float Bo = __shfl_down_sync(0xFFFFFFFFu, B, d);
        B = fmaf(B, Ao, Bo);
        A *= Ao;
    }

    __syncthreads();   // bufs free: reuse as q transpose buffer
    if ((t & 31) == 0) { sAW[t >> 5] = A; sBW[t >> 5] = B; }
    if (t == F_THR - 1)
        g_tail[b] = make_float4(qbuf[OWN - 4], qbuf[OWN - 3], qbuf[OWN - 2], qbuf[OWN - 1]);

    float* qtr = &bufs[0][0];            // SPAD(2047)+2 = 2113 <= 3456 floats
#pragma unroll
    for (int e = 0; e < OWN; ++e) qtr[spad(sLoc + e)] = qbuf[e];
    __syncthreads();

    if (t == 0) {
        float aa = sAW[0], bb = sBW[0];
#pragma unroll
        for (int w = 1; w < 8; ++w) {
            bb = fmaf(bb, sAW[w], sBW[w]);
            aa *= sAW[w];
        }
        g_agg[b] = make_float2(aa, bb);
    }

    // coalesced q write-out
#pragma unroll
    for (int k = 0; k < OWN; ++k) {
        const int i = k * F_THR + t;
        g_q[rowBase + i] = qtr[spad(i)];
    }
}

// ---------------------------------------------------------------------------
// K2: apply. Block computes its own incoming h (ordered masked reduction over
// published pairs, identity for j >= blk), then local scan + output.
// full pair of block j = P_tail(last `shift` q of block j-1) o P_own(j)
// combine(first f, then g): A = fA*gA, B = fB*gA + gB
// ---------------------------------------------------------------------------
__global__ void __launch_bounds__(F_THR) k_apply(
    const float* __restrict__ x,
    const float* __restrict__ wr1p, const float* __restrict__ wr2p,
    const float* __restrict__ wz1p, const float* __restrict__ wz2p,
    const void*  __restrict__ epochp,
    float* __restrict__ out)
{
    __shared__ float sq[SPAD(R_BLK - 1) + 2];
    __shared__ float sWA[8], sWB[8];
    __shared__ float sHB;

    const int blk  = blockIdx.x;
    const int t    = threadIdx.x;
    const int lane = t & 31;
    const int wid  = t >> 5;

    const float wr1 = wr1p[0], wr2 = wr2p[0];
    const float wz1 = wz1p[0], wz2 = wz2p[0];

    int epoch;
    {
        const int iv = *reinterpret_cast<const int*>(epochp);
        if (iv >= 0 && iv < 1000000) epoch = iv;
        else epoch = (int)(*reinterpret_cast<const float*>(epochp));
    }
    const bool pass2 = (epoch > 10);

    const float rid  = rintf(x[8]);
    const int  shift = (rid == 3723.0f || rid == 870.0f) ? 1 : 4;

    const int gbase = blk * R_BLK;

    // ---- stage q_shift (coalesced) ----
#pragma unroll
    for (int k = 0; k < OWN; ++k) {
        const int i = k * F_THR + t;
        const int j = gbase + i - shift;
        sq[spad(i)] = (j >= 0) ? g_q[j] : 0.0f;
    }

    // ---- incoming h: ordered masked reduction of full pairs j in [0, blk) ----
    // thread t owns pairs j = 2t, 2t+1 (contiguous -> order preserved)
    float A = 1.0f, B = 0.0f;
#pragma unroll
    for (int k = 0; k < 2; ++k) {
        const int j = 2 * t + k;
        if (j < blk) {
            const float2 ag = g_agg[j];
            float tl[4] = {0.f, 0.f, 0.f, 0.f};
            if (j > 0) {
                const float4 v = g_tail[j - 1];
                tl[0] = v.x; tl[1] = v.y; tl[2] = v.z; tl[3] = v.w;
            }
            float At = 1.0f, Bt = 0.0f;
            for (int i = 0; i < shift; ++i) {
                Bt = fmaf(Bt, wr1, wr2 * tl[4 - shift + i]);
                At *= wr1;
            }
            const float fA = At * ag.x;
            const float fB = fmaf(Bt, ag.x, ag.y);
            B = fmaf(B, fA, fB);
            A *= fA;
        }
    }
#pragma unroll
    for (int d = 1; d < 32; d <<= 1) {
        const float Ao = __shfl_down_sync(0xFFFFFFFFu, A, d);
        const float Bo = __shfl_down_sync(0xFFFFFFFFu, B, d);
        B = fmaf(B, Ao, Bo);
        A *= Ao;
    }
    if (lane == 0) { sWA[wid] = A; sWB[wid] = B; }
    __syncthreads();         // also orders the sq[] staging writes
    if (t == 0) {
        float aa = sWA[0], bb = sWB[0];
#pragma unroll
        for (int w = 1; w < 8; ++w) {
            bb = fmaf(bb, sWA[w], sWB[w]);
            aa *= sWA[w];
        }
        sHB = bb;            // incoming h for this block (h0 = 0)
    }
    __syncthreads();

    // ---- local hierarchical scan ----
    const int tb = t * OWN;
    float qv[OWN];
    float lA = 1.0f, lB = 0.0f;
#pragma unroll
    for (int e = 0; e < OWN; ++e) {
        const float q = sq[spad(tb + e)];
        qv[e] = q;
        lB = fmaf(lB, wr1, wr2 * q);
        lA *= wr1;
    }

#pragma unroll
    for (int d = 1; d < 32; d <<= 1) {
        const float pa = __shfl_up_sync(0xFFFFFFFFu, lA, d);
        const float pb = __shfl_up_sync(0xFFFFFFFFu, lB, d);
        if (lane >= d) { lB = fmaf(pb, lA, lB); lA *= pa; }
    }
    float eA = __shfl_up_sync(0xFFFFFFFFu, lA, 1);
    float eB = __shfl_up_sync(0xFFFFFFFFu, lB, 1);
    if (lane == 0) { eA = 1.0f; eB = 0.0f; }
    if (lane == 31) { sWA[wid] = lA; sWB[wid] = lB; }
    __syncthreads();

    if (t == 0) {
        float aa = 1.0f, bb = 0.0f;
#pragma unroll
        for (int w = 0; w < 8; ++w) {
            const float ta = sWA[w], tb2 = sWB[w];
            sWA[w] = aa; sWB[w] = bb;
            bb = fmaf(bb, ta, tb2);
            aa *= ta;
        }
    }
    __syncthreads();

    const float hb = sHB;
    const float hw = fmaf(hb, sWA[wid], sWB[wid]);
    float h = fmaf(hw, eA, eB);

#pragma unroll
    for (int e = 0; e < OWN; ++e) {
        const float q = qv[e];
        h = fmaf(h, wr1, wr2 * q);
        const float o = fmaf(h, wz1, wz2 * q);
        sq[spad(tb + e)] = pass2 ? o : q;
    }
    __syncthreads();

#pragma unroll
    for (int k = 0; k < OWN; ++k) {
        const int i = k * F_THR + t;
        out[gbase + i] = sq[spad(i)];
    }
}

// ---------------------------------------------------------------------------
// kernel_launch
// ---------------------------------------------------------------------------
extern "C" void kernel_launch(void* const* d_in, const int* in_sizes, int n_in,
                              void* d_out, int out_size)
{
    (void)in_sizes; (void)n_in; (void)out_size;
    const float* x    = (const float*)d_in[0];
    const float* f0p  = (const float*)d_in[1];
    const float* fcp  = (const float*)d_in[2];
    const float* kp   = (const float*)d_in[3];
    const float* np   = (const float*)d_in[4];
    const float* dpp  = (const float*)d_in[5];
    const float* evp  = (const float*)d_in[6];
    const float* evcp = (const float*)d_in[7];
    const float* mrp  = (const float*)d_in[8];
    const float* missp= (const float*)d_in[9];
    const float* wr1p = (const float*)d_in[10];
    const float* wr2p = (const float*)d_in[11];
    const float* wz1p = (const float*)d_in[12];
    const float* wz2p = (const float*)d_in[13];
    const void*  epochp = d_in[14];
    float* out = (float*)d_out;

    k_fused<<<F_BLKS, F_THR>>>(x, f0p, fcp, kp, np, evp, evcp, mrp, missp, dpp,
                               wr1p, wr2p);
    k_apply<<<F_BLKS, F_THR>>>(x, wr1p, wr2p, wz1p, wz2p, epochp, out);
}